// round 14
// baseline (speedup 1.0000x reference)
#include <cuda_runtime.h>
#include <cuda_fp16.h>
#include <math.h>

#define NMAX 100000
#define EMAX 1600000
#define FIN  128
#define F1   64
#define F2   40
#define NB   ((NMAX + 1023) / 1024)   // 98 scan blocks

// ---------------- scratch (device globals) ---------------------------------
__device__ int    g_is64;                // 1 if edge_index is int64, 0 if int32
__device__ int    g_bar1, g_bar2;        // grid-barrier counters (reset per call)
__device__ int    g_cnt [NMAX];
__device__ int    g_off [NMAX + 1];
__device__ int    g_pos [NMAX];
__device__ int    g_bsum[NB];
__device__ int    g_eidx[EMAX];          // src ids sorted by dst
__device__ float  g_dinv[NMAX];
__device__ uint4  g_xwh [(size_t)NMAX * 8];       // RAW x@W1, fp16 (32 uints/row)
__device__ float4 g_h   [(size_t)NMAX * F1 / 4];  // relu output (fp32)
__device__ uint4  g_hwsh[(size_t)NMAX * 5];       // (h@W2)*dinv, fp16 (20 uints/row)

// ---------------- fused: zero counters/barriers + dtype probe ---------------
__global__ void k_zero_probe(const int* __restrict__ ei32, int E, int n) {
    if (blockIdx.x == 0) {
        int t = threadIdx.x;
        if (t == 0) { g_bar1 = 0; g_bar2 = 0; }
        int nz = 0;
        int lim = (E < 1024) ? E : 1024;
        for (int i = t; i < lim; i += 256) nz |= ei32[2 * i + 1];
        int any = __syncthreads_or(nz);
        if (t == 0) g_is64 = (any == 0) ? 1 : 0;
    } else {
        int i = (blockIdx.x - 1) * 256 + threadIdx.x;
        if (i < n) { g_cnt[i] = 0; g_pos[i] = 0; }
    }
}

// ---------------- fused: GEMM1 (raw, fp16 out) + degree histogram -----------
__global__ void __launch_bounds__(256)
k_gemm1_hist(const float* __restrict__ x, const float* __restrict__ W,
             const int* __restrict__ ei32, int E, int n, int gemmBlocks) {
    __shared__ float ws[FIN * F1];  // 32 KB (idle for hist role)
    int tid = threadIdx.x;

    if (blockIdx.x >= gemmBlocks) {
        int e = (blockIdx.x - gemmBlocks) * 256 + tid;
        if (e >= E) return;
        int d;
        if (g_is64) d = (int)(((const long long*)ei32) + E)[e];
        else        d = ei32[E + e];
        if ((unsigned)d < (unsigned)n) atomicAdd(&g_cnt[d], 1);
        return;
    }

    for (int i = tid; i < FIN * F1 / 4; i += 256)
        ((float4*)ws)[i] = ((const float4*)W)[i];
    __syncthreads();

    int sub = tid >> 3;
    int cg  = (tid & 7) * 8;
    int base = blockIdx.x * 128 + sub;

    float a[4][8];
#pragma unroll
    for (int r = 0; r < 4; r++)
#pragma unroll
        for (int j = 0; j < 8; j++) a[r][j] = 0.0f;

    const float4* xr[4];
#pragma unroll
    for (int r = 0; r < 4; r++) {
        int row = base + r * 32;
        int rc = (row < n) ? row : (n - 1);
        xr[r] = (const float4*)(x + (size_t)rc * FIN);
    }

#pragma unroll 4
    for (int k4 = 0; k4 < FIN / 4; k4++) {
        float4 xv[4];
#pragma unroll
        for (int r = 0; r < 4; r++) xv[r] = xr[r][k4];
#pragma unroll
        for (int kk = 0; kk < 4; kk++) {
            const float4* wr = (const float4*)(ws + (k4 * 4 + kk) * F1 + cg);
            float4 wa = wr[0];
            float4 wb = wr[1];
#pragma unroll
            for (int r = 0; r < 4; r++) {
                float p = (kk == 0) ? xv[r].x : (kk == 1) ? xv[r].y
                        : (kk == 2) ? xv[r].z : xv[r].w;
                a[r][0] = fmaf(p, wa.x, a[r][0]);
                a[r][1] = fmaf(p, wa.y, a[r][1]);
                a[r][2] = fmaf(p, wa.z, a[r][2]);
                a[r][3] = fmaf(p, wa.w, a[r][3]);
                a[r][4] = fmaf(p, wb.x, a[r][4]);
                a[r][5] = fmaf(p, wb.y, a[r][5]);
                a[r][6] = fmaf(p, wb.z, a[r][6]);
                a[r][7] = fmaf(p, wb.w, a[r][7]);
            }
        }
    }

#pragma unroll
    for (int r = 0; r < 4; r++) {
        int row = base + r * 32;
        if (row >= n) break;
        __half2 h0 = __float22half2_rn(make_float2(a[r][0], a[r][1]));
        __half2 h1 = __float22half2_rn(make_float2(a[r][2], a[r][3]));
        __half2 h2 = __float22half2_rn(make_float2(a[r][4], a[r][5]));
        __half2 h3 = __float22half2_rn(make_float2(a[r][6], a[r][7]));
        uint4 pk;
        pk.x = *(unsigned*)&h0; pk.y = *(unsigned*)&h1;
        pk.z = *(unsigned*)&h2; pk.w = *(unsigned*)&h3;
        ((uint4*)g_xwh)[(size_t)row * 8 + (cg >> 3)] = pk;
    }
}

// ---------------- fused scan + place (grid-resident, 98 blocks) -------------
__device__ __forceinline__ void grid_barrier(int* ctr, int nb) {
    __syncthreads();
    if (threadIdx.x == 0) {
        __threadfence();
        atomicAdd(ctr, 1);
        while (atomicAdd(ctr, 0) < nb) { }
        __threadfence();
    }
    __syncthreads();
}

__global__ void __launch_bounds__(1024)
k_scan_place(const int* __restrict__ ei32, int E, int n, int nb) {
    __shared__ int sh[2][1024];
    __shared__ int boff_sh;
    int tid = threadIdx.x;
    int i = blockIdx.x * 1024 + tid;

    // phase 1: local exclusive scan of g_cnt
    int x = (i < n) ? g_cnt[i] : 0;
    sh[0][tid] = x;
    int pin = 0;
    for (int off = 1; off < 1024; off <<= 1) {
        __syncthreads();
        int v = sh[pin][tid];
        if (tid >= off) v += sh[pin][tid - off];
        sh[1 - pin][tid] = v;
        pin = 1 - pin;
    }
    __syncthreads();
    int inc = sh[pin][tid];
    if (i < n) g_off[i] = inc - x;             // local exclusive
    if (tid == 1023) g_bsum[blockIdx.x] = inc; // block total

    grid_barrier(&g_bar1, nb);

    // phase 2: add block prefix, compute dinv
    if (tid == 0) {
        int run = 0;
        for (int b = 0; b < blockIdx.x; b++) run += g_bsum[b];
        boff_sh = run;
        if (blockIdx.x == nb - 1) g_off[n] = run + g_bsum[nb - 1];
    }
    __syncthreads();
    if (i < n) {
        g_off[i] += boff_sh;
        g_dinv[i] = rsqrtf((float)(g_cnt[i] + 1));   // +1 self-loop
    }

    grid_barrier(&g_bar2, nb);

    // phase 3: place edges (grid-stride over E)
    int stride = nb * 1024;
    for (int e = blockIdx.x * 1024 + tid; e < E; e += stride) {
        int d, s;
        if (g_is64) {
            const long long* e64 = (const long long*)ei32;
            d = (int)e64[E + e];
            s = (int)e64[e];
        } else {
            d = ei32[E + e];
            s = ei32[e];
        }
        if ((unsigned)d >= (unsigned)n) continue;
        if ((unsigned)s >= (unsigned)n) s = 0;
        int slot = g_off[d] + atomicAdd(&g_pos[d], 1);
        if (slot < EMAX) g_eidx[slot] = s;
    }
}

// ---------------- aggregation layer1 (warp/node, fp16 gather, 8-edge MLP) ---
__global__ void k_agg1(const float* __restrict__ b1, int n) {
    int lane = threadIdx.x & 31;
    int w = blockIdx.x * 8 + (threadIdx.x >> 5);
    if (w >= n) return;

    const unsigned* xw = (const unsigned*)g_xwh;   // 32 uints per row
    int beg = g_off[w], end = g_off[w + 1];

    float accx = 0.f, accy = 0.f;
    int k = beg;
    for (; k + 7 < end; k += 8) {
        int s0 = g_eidx[k],     s1 = g_eidx[k + 1];
        int s2 = g_eidx[k + 2], s3 = g_eidx[k + 3];
        int s4 = g_eidx[k + 4], s5 = g_eidx[k + 5];
        int s6 = g_eidx[k + 6], s7 = g_eidx[k + 7];
        float d0 = g_dinv[s0], d1 = g_dinv[s1], d2 = g_dinv[s2], d3 = g_dinv[s3];
        float d4 = g_dinv[s4], d5 = g_dinv[s5], d6 = g_dinv[s6], d7 = g_dinv[s7];
        unsigned u0 = xw[(size_t)s0 * 32 + lane];
        unsigned u1 = xw[(size_t)s1 * 32 + lane];
        unsigned u2 = xw[(size_t)s2 * 32 + lane];
        unsigned u3 = xw[(size_t)s3 * 32 + lane];
        unsigned u4 = xw[(size_t)s4 * 32 + lane];
        unsigned u5 = xw[(size_t)s5 * 32 + lane];
        unsigned u6 = xw[(size_t)s6 * 32 + lane];
        unsigned u7 = xw[(size_t)s7 * 32 + lane];
        float2 f0 = __half22float2(*(__half2*)&u0);
        float2 f1 = __half22float2(*(__half2*)&u1);
        float2 f2 = __half22float2(*(__half2*)&u2);
        float2 f3 = __half22float2(*(__half2*)&u3);
        float2 f4 = __half22float2(*(__half2*)&u4);
        float2 f5 = __half22float2(*(__half2*)&u5);
        float2 f6 = __half22float2(*(__half2*)&u6);
        float2 f7 = __half22float2(*(__half2*)&u7);
        accx = fmaf(d0, f0.x, accx); accy = fmaf(d0, f0.y, accy);
        accx = fmaf(d1, f1.x, accx); accy = fmaf(d1, f1.y, accy);
        accx = fmaf(d2, f2.x, accx); accy = fmaf(d2, f2.y, accy);
        accx = fmaf(d3, f3.x, accx); accy = fmaf(d3, f3.y, accy);
        accx = fmaf(d4, f4.x, accx); accy = fmaf(d4, f4.y, accy);
        accx = fmaf(d5, f5.x, accx); accy = fmaf(d5, f5.y, accy);
        accx = fmaf(d6, f6.x, accx); accy = fmaf(d6, f6.y, accy);
        accx = fmaf(d7, f7.x, accx); accy = fmaf(d7, f7.y, accy);
    }
    for (; k < end; k++) {
        int s = g_eidx[k];
        float ds = g_dinv[s];
        unsigned u = xw[(size_t)s * 32 + lane];
        float2 f = __half22float2(*(__half2*)&u);
        accx = fmaf(ds, f.x, accx);
        accy = fmaf(ds, f.y, accy);
    }

    float sc = g_dinv[w];
    unsigned su = xw[(size_t)w * 32 + lane];        // self-loop
    float2 sf = __half22float2(*(__half2*)&su);
    accx = fmaf(sc, sf.x, accx);
    accy = fmaf(sc, sf.y, accy);

    float bx = b1[2 * lane], by = b1[2 * lane + 1];
    float2 r;
    r.x = fmaxf(fmaf(accx, sc, bx), 0.0f);
    r.y = fmaxf(fmaf(accy, sc, by), 0.0f);
    ((float2*)g_h)[(size_t)w * 32 + lane] = r;
}

// ---------------- GEMM2: hws = (h @ W2) * dinv[row], fp16 out ---------------
__global__ void k_gemm2(const float* __restrict__ W, int n) {
    __shared__ float ws[F1 * F2];  // 10.24 KB
    int tid = threadIdx.x;
    for (int i = tid; i < F1 * F2; i += 320) ws[i] = W[i];
    __syncthreads();

    int sub = tid / 5;
    int cg  = (tid % 5) * 8;
    int r0 = blockIdx.x * 128 + sub;
    int r1 = r0 + 64;
    if (r0 >= n) return;
    bool v1 = (r1 < n);

    float a00 = 0.f, a01 = 0.f, a02 = 0.f, a03 = 0.f;
    float a04 = 0.f, a05 = 0.f, a06 = 0.f, a07 = 0.f;
    float a10 = 0.f, a11 = 0.f, a12 = 0.f, a13 = 0.f;
    float a14 = 0.f, a15 = 0.f, a16 = 0.f, a17 = 0.f;

    const float4* hr0 = (const float4*)((const float*)g_h + (size_t)r0 * F1);
    const float4* hr1 = (const float4*)((const float*)g_h + (size_t)(v1 ? r1 : r0) * F1);
#pragma unroll 4
    for (int k4 = 0; k4 < F1 / 4; k4++) {
        float4 ha = hr0[k4];
        float4 hb = hr1[k4];
        float h0[4] = {ha.x, ha.y, ha.z, ha.w};
        float h1[4] = {hb.x, hb.y, hb.z, hb.w};
#pragma unroll
        for (int kk = 0; kk < 4; kk++) {
            const float4* wr = (const float4*)(ws + (k4 * 4 + kk) * F2 + cg);
            float4 wa = wr[0];
            float4 wb = wr[1];
            float p0 = h0[kk], p1 = h1[kk];
            a00 = fmaf(p0, wa.x, a00); a10 = fmaf(p1, wa.x, a10);
            a01 = fmaf(p0, wa.y, a01); a11 = fmaf(p1, wa.y, a11);
            a02 = fmaf(p0, wa.z, a02); a12 = fmaf(p1, wa.z, a12);
            a03 = fmaf(p0, wa.w, a03); a13 = fmaf(p1, wa.w, a13);
            a04 = fmaf(p0, wb.x, a04); a14 = fmaf(p1, wb.x, a14);
            a05 = fmaf(p0, wb.y, a05); a15 = fmaf(p1, wb.y, a15);
            a06 = fmaf(p0, wb.z, a06); a16 = fmaf(p1, wb.z, a16);
            a07 = fmaf(p0, wb.w, a07); a17 = fmaf(p1, wb.w, a17);
        }
    }

    float s0 = g_dinv[r0];
    {
        __half2 h0 = __float22half2_rn(make_float2(a00 * s0, a01 * s0));
        __half2 h1 = __float22half2_rn(make_float2(a02 * s0, a03 * s0));
        __half2 h2 = __float22half2_rn(make_float2(a04 * s0, a05 * s0));
        __half2 h3 = __float22half2_rn(make_float2(a06 * s0, a07 * s0));
        uint4 pk;
        pk.x = *(unsigned*)&h0; pk.y = *(unsigned*)&h1;
        pk.z = *(unsigned*)&h2; pk.w = *(unsigned*)&h3;
        ((uint4*)g_hwsh)[(size_t)r0 * 5 + (cg >> 3)] = pk;
    }
    if (v1) {
        float s1 = g_dinv[r1];
        __half2 h0 = __float22half2_rn(make_float2(a10 * s1, a11 * s1));
        __half2 h1 = __float22half2_rn(make_float2(a12 * s1, a13 * s1));
        __half2 h2 = __float22half2_rn(make_float2(a14 * s1, a15 * s1));
        __half2 h3 = __float22half2_rn(make_float2(a16 * s1, a17 * s1));
        uint4 pk;
        pk.x = *(unsigned*)&h0; pk.y = *(unsigned*)&h1;
        pk.z = *(unsigned*)&h2; pk.w = *(unsigned*)&h3;
        ((uint4*)g_hwsh)[(size_t)r1 * 5 + (cg >> 3)] = pk;
    }
}

// ---------------- aggregation layer2 + bias + log_softmax (fp16 gather) ----
__global__ void k_agg2(const float* __restrict__ b2, float* __restrict__ out, int n) {
    int lane = threadIdx.x & 31;
    int w = blockIdx.x * 8 + (threadIdx.x >> 5);
    if (w >= n) return;

    bool act = (lane < F2 / 2);
    int li = act ? lane : 0;
    const unsigned* hw = (const unsigned*)g_hwsh;   // 20 uints per row
    int beg = g_off[w], end = g_off[w + 1];

    float accx = 0.f, accy = 0.f;
    int k = beg;
    for (; k + 7 < end; k += 8) {
        int s0 = g_eidx[k],     s1 = g_eidx[k + 1];
        int s2 = g_eidx[k + 2], s3 = g_eidx[k + 3];
        int s4 = g_eidx[k + 4], s5 = g_eidx[k + 5];
        int s6 = g_eidx[k + 6], s7 = g_eidx[k + 7];
        unsigned u0 = hw[(size_t)s0 * 20 + li];
        unsigned u1 = hw[(size_t)s1 * 20 + li];
        unsigned u2 = hw[(size_t)s2 * 20 + li];
        unsigned u3 = hw[(size_t)s3 * 20 + li];
        unsigned u4 = hw[(size_t)s4 * 20 + li];
        unsigned u5 = hw[(size_t)s5 * 20 + li];
        unsigned u6 = hw[(size_t)s6 * 20 + li];
        unsigned u7 = hw[(size_t)s7 * 20 + li];
        float2 f0 = __half22float2(*(__half2*)&u0);
        float2 f1 = __half22float2(*(__half2*)&u1);
        float2 f2 = __half22float2(*(__half2*)&u2);
        float2 f3 = __half22float2(*(__half2*)&u3);
        float2 f4 = __half22float2(*(__half2*)&u4);
        float2 f5 = __half22float2(*(__half2*)&u5);
        float2 f6 = __half22float2(*(__half2*)&u6);
        float2 f7 = __half22float2(*(__half2*)&u7);
        accx += ((f0.x + f1.x) + (f2.x + f3.x)) + ((f4.x + f5.x) + (f6.x + f7.x));
        accy += ((f0.y + f1.y) + (f2.y + f3.y)) + ((f4.y + f5.y) + (f6.y + f7.y));
    }
    for (; k < end; k++) {
        unsigned u = hw[(size_t)g_eidx[k] * 20 + li];
        float2 f = __half22float2(*(__half2*)&u);
        accx += f.x;
        accy += f.y;
    }

    {
        unsigned su = hw[(size_t)w * 20 + li];
        float2 sf = __half22float2(*(__half2*)&su);
        accx += sf.x;
        accy += sf.y;
    }

    float sc = g_dinv[w];
    float zx = fmaf(accx, sc, b2[2 * li]);
    float zy = fmaf(accy, sc, b2[2 * li + 1]);

    float m = act ? fmaxf(zx, zy) : -1e30f;
#pragma unroll
    for (int o = 16; o > 0; o >>= 1)
        m = fmaxf(m, __shfl_xor_sync(0xFFFFFFFFu, m, o));

    float sum = act ? (expf(zx - m) + expf(zy - m)) : 0.0f;
#pragma unroll
    for (int o = 16; o > 0; o >>= 1)
        sum += __shfl_xor_sync(0xFFFFFFFFu, sum, o);

    float lse = m + logf(sum);
    if (act) {
        float2* o2 = (float2*)(out + (size_t)w * F2 + 2 * li);
        *o2 = make_float2(zx - lse, zy - lse);
    }
}

// ---------------- launcher --------------------------------------------------
extern "C" void kernel_launch(void* const* d_in, const int* in_sizes, int n_in,
                              void* d_out, int out_size) {
    const float* x    = (const float*)d_in[0];
    const int*   ei32 = (const int*)d_in[1];
    const float* W1   = (const float*)d_in[2];
    const float* b1   = (const float*)d_in[3];
    const float* W2   = (const float*)d_in[4];
    const float* b2   = (const float*)d_in[5];
    float*       out  = (float*)d_out;

    int n = in_sizes[0] / FIN;       // 100000
    int E = in_sizes[1] / 2;         // 1600000

    const int B = 256;
    int gn = (n + B - 1) / B;
    int ge = (E + B - 1) / B;
    int nb = (n + 1023) / 1024;      // 98
    int ga = (n + 7) / 8;
    int gemmBlocks = (n + 127) / 128;

    k_zero_probe <<<gn + 1, B>>>(ei32, E, n);
    k_gemm1_hist <<<gemmBlocks + ge, B>>>(x, W1, ei32, E, n, gemmBlocks);
    k_scan_place <<<nb, 1024>>>(ei32, E, n, nb);
    k_agg1       <<<ga, B>>>(b1, n);           // 4th launch -> ncu captures this
    k_gemm2      <<<(n + 127) / 128, 320>>>(W2, n);
    k_agg2       <<<ga, B>>>(b2, out, n);
}

// round 15
// speedup vs baseline: 1.0493x; 1.0493x over previous
#include <cuda_runtime.h>
#include <cuda_fp16.h>
#include <math.h>

#define NMAX 100000
#define EMAX 1600000
#define FIN  128
#define F1   64
#define F2   40
#define NB   ((NMAX + 1023) / 1024)   // 98 scan blocks

// ---------------- scratch (device globals) ---------------------------------
__device__ int    g_is64;
__device__ int    g_bar1;                // grid-barrier counter (reset per call)
__device__ int    g_cnt [NMAX];
__device__ int    g_off [NMAX + 1];
__device__ int    g_pos [NMAX];
__device__ int    g_bsum[NB];
__device__ int    g_eidx[EMAX];          // src ids sorted by dst
__device__ float  g_dinv[NMAX];
__device__ uint4  g_xwh [(size_t)NMAX * 8];       // RAW x@W1, fp16 (32 uints/row)
__device__ float4 g_h   [(size_t)NMAX * F1 / 4];  // relu output (fp32)
__device__ uint4  g_hwsh[(size_t)NMAX * 5];       // (h@W2)*dinv, fp16 (20 uints/row)

// ---------------- fused: zero counters/barrier + dtype probe ----------------
__global__ void k_zero_probe(const int* __restrict__ ei32, int E, int n) {
    if (blockIdx.x == 0) {
        int t = threadIdx.x;
        if (t == 0) g_bar1 = 0;
        int nz = 0;
        int lim = (E < 1024) ? E : 1024;
        for (int i = t; i < lim; i += 256) nz |= ei32[2 * i + 1];
        int any = __syncthreads_or(nz);
        if (t == 0) g_is64 = (any == 0) ? 1 : 0;
    } else {
        int i = (blockIdx.x - 1) * 256 + threadIdx.x;
        if (i < n) { g_cnt[i] = 0; g_pos[i] = 0; }
    }
}

// ---------------- fused: GEMM1 (raw, fp16 out) + degree histogram -----------
__global__ void __launch_bounds__(256)
k_gemm1_hist(const float* __restrict__ x, const float* __restrict__ W,
             const int* __restrict__ ei32, int E, int n, int gemmBlocks) {
    __shared__ float ws[FIN * F1];  // 32 KB (idle for hist role)
    int tid = threadIdx.x;

    if (blockIdx.x >= gemmBlocks) {
        int e = (blockIdx.x - gemmBlocks) * 256 + tid;
        if (e >= E) return;
        int d;
        if (g_is64) d = (int)(((const long long*)ei32) + E)[e];
        else        d = ei32[E + e];
        if ((unsigned)d < (unsigned)n) atomicAdd(&g_cnt[d], 1);
        return;
    }

    for (int i = tid; i < FIN * F1 / 4; i += 256)
        ((float4*)ws)[i] = ((const float4*)W)[i];
    __syncthreads();

    int sub = tid >> 3;
    int cg  = (tid & 7) * 8;
    int base = blockIdx.x * 128 + sub;

    float a[4][8];
#pragma unroll
    for (int r = 0; r < 4; r++)
#pragma unroll
        for (int j = 0; j < 8; j++) a[r][j] = 0.0f;

    const float4* xr[4];
#pragma unroll
    for (int r = 0; r < 4; r++) {
        int row = base + r * 32;
        int rc = (row < n) ? row : (n - 1);
        xr[r] = (const float4*)(x + (size_t)rc * FIN);
    }

#pragma unroll 4
    for (int k4 = 0; k4 < FIN / 4; k4++) {
        float4 xv[4];
#pragma unroll
        for (int r = 0; r < 4; r++) xv[r] = xr[r][k4];
#pragma unroll
        for (int kk = 0; kk < 4; kk++) {
            const float4* wr = (const float4*)(ws + (k4 * 4 + kk) * F1 + cg);
            float4 wa = wr[0];
            float4 wb = wr[1];
#pragma unroll
            for (int r = 0; r < 4; r++) {
                float p = (kk == 0) ? xv[r].x : (kk == 1) ? xv[r].y
                        : (kk == 2) ? xv[r].z : xv[r].w;
                a[r][0] = fmaf(p, wa.x, a[r][0]);
                a[r][1] = fmaf(p, wa.y, a[r][1]);
                a[r][2] = fmaf(p, wa.z, a[r][2]);
                a[r][3] = fmaf(p, wa.w, a[r][3]);
                a[r][4] = fmaf(p, wb.x, a[r][4]);
                a[r][5] = fmaf(p, wb.y, a[r][5]);
                a[r][6] = fmaf(p, wb.z, a[r][6]);
                a[r][7] = fmaf(p, wb.w, a[r][7]);
            }
        }
    }

#pragma unroll
    for (int r = 0; r < 4; r++) {
        int row = base + r * 32;
        if (row >= n) break;
        __half2 h0 = __float22half2_rn(make_float2(a[r][0], a[r][1]));
        __half2 h1 = __float22half2_rn(make_float2(a[r][2], a[r][3]));
        __half2 h2 = __float22half2_rn(make_float2(a[r][4], a[r][5]));
        __half2 h3 = __float22half2_rn(make_float2(a[r][6], a[r][7]));
        uint4 pk;
        pk.x = *(unsigned*)&h0; pk.y = *(unsigned*)&h1;
        pk.z = *(unsigned*)&h2; pk.w = *(unsigned*)&h3;
        ((uint4*)g_xwh)[(size_t)row * 8 + (cg >> 3)] = pk;
    }
}

// ---------------- fused scan (grid-resident, 98 blocks, 1 barrier) ----------
__device__ __forceinline__ void grid_barrier(int* ctr, int nb) {
    __syncthreads();
    if (threadIdx.x == 0) {
        __threadfence();
        atomicAdd(ctr, 1);
        while (atomicAdd(ctr, 0) < nb) { }
        __threadfence();
    }
    __syncthreads();
}

__global__ void __launch_bounds__(1024)
k_scan(int n, int nb) {
    __shared__ int sh[2][1024];
    __shared__ int boff_sh;
    int tid = threadIdx.x;
    int i = blockIdx.x * 1024 + tid;

    int x = (i < n) ? g_cnt[i] : 0;
    sh[0][tid] = x;
    int pin = 0;
    for (int off = 1; off < 1024; off <<= 1) {
        __syncthreads();
        int v = sh[pin][tid];
        if (tid >= off) v += sh[pin][tid - off];
        sh[1 - pin][tid] = v;
        pin = 1 - pin;
    }
    __syncthreads();
    int inc = sh[pin][tid];
    if (i < n) g_off[i] = inc - x;
    if (tid == 1023) g_bsum[blockIdx.x] = inc;

    grid_barrier(&g_bar1, nb);

    if (tid == 0) {
        int run = 0;
        for (int b = 0; b < blockIdx.x; b++) run += g_bsum[b];
        boff_sh = run;
        if (blockIdx.x == nb - 1) g_off[n] = run + g_bsum[nb - 1];
    }
    __syncthreads();
    if (i < n) {
        g_off[i] += boff_sh;
        g_dinv[i] = rsqrtf((float)(g_cnt[i] + 1));   // +1 self-loop
    }
}

// ---------------- place (wide, 4th launch -> profiled) ----------------------
__global__ void k_place(const int* __restrict__ ei32, int E, int n) {
    int e = blockIdx.x * blockDim.x + threadIdx.x;
    if (e >= E) return;
    int d, s;
    if (g_is64) {
        const long long* e64 = (const long long*)ei32;
        d = (int)e64[E + e];
        s = (int)e64[e];
    } else {
        d = ei32[E + e];
        s = ei32[e];
    }
    if ((unsigned)d >= (unsigned)n) return;
    if ((unsigned)s >= (unsigned)n) s = 0;
    int slot = g_off[d] + atomicAdd(&g_pos[d], 1);
    if (slot < EMAX) g_eidx[slot] = s;
}

// ---------------- aggregation layer1 (32-bit addressing, 8-edge MLP) --------
__global__ void k_agg1(const float* __restrict__ b1, int n) {
    int lane = threadIdx.x & 31;
    int w = blockIdx.x * 8 + (threadIdx.x >> 5);
    if (w >= n) return;

    const unsigned* xwl = ((const unsigned*)g_xwh) + lane;  // lane base
    int beg = g_off[w], end = g_off[w + 1];

    float accx = 0.f, accy = 0.f;
    int k = beg;
    for (; k + 7 < end; k += 8) {
        unsigned o0 = (unsigned)g_eidx[k]     << 5;
        unsigned o1 = (unsigned)g_eidx[k + 1] << 5;
        unsigned o2 = (unsigned)g_eidx[k + 2] << 5;
        unsigned o3 = (unsigned)g_eidx[k + 3] << 5;
        unsigned o4 = (unsigned)g_eidx[k + 4] << 5;
        unsigned o5 = (unsigned)g_eidx[k + 5] << 5;
        unsigned o6 = (unsigned)g_eidx[k + 6] << 5;
        unsigned o7 = (unsigned)g_eidx[k + 7] << 5;
        float d0 = g_dinv[o0 >> 5], d1 = g_dinv[o1 >> 5];
        float d2 = g_dinv[o2 >> 5], d3 = g_dinv[o3 >> 5];
        float d4 = g_dinv[o4 >> 5], d5 = g_dinv[o5 >> 5];
        float d6 = g_dinv[o6 >> 5], d7 = g_dinv[o7 >> 5];
        unsigned u0 = xwl[o0];
        unsigned u1 = xwl[o1];
        unsigned u2 = xwl[o2];
        unsigned u3 = xwl[o3];
        unsigned u4 = xwl[o4];
        unsigned u5 = xwl[o5];
        unsigned u6 = xwl[o6];
        unsigned u7 = xwl[o7];
        float2 f0 = __half22float2(*(__half2*)&u0);
        float2 f1 = __half22float2(*(__half2*)&u1);
        float2 f2 = __half22float2(*(__half2*)&u2);
        float2 f3 = __half22float2(*(__half2*)&u3);
        float2 f4 = __half22float2(*(__half2*)&u4);
        float2 f5 = __half22float2(*(__half2*)&u5);
        float2 f6 = __half22float2(*(__half2*)&u6);
        float2 f7 = __half22float2(*(__half2*)&u7);
        accx = fmaf(d0, f0.x, accx); accy = fmaf(d0, f0.y, accy);
        accx = fmaf(d1, f1.x, accx); accy = fmaf(d1, f1.y, accy);
        accx = fmaf(d2, f2.x, accx); accy = fmaf(d2, f2.y, accy);
        accx = fmaf(d3, f3.x, accx); accy = fmaf(d3, f3.y, accy);
        accx = fmaf(d4, f4.x, accx); accy = fmaf(d4, f4.y, accy);
        accx = fmaf(d5, f5.x, accx); accy = fmaf(d5, f5.y, accy);
        accx = fmaf(d6, f6.x, accx); accy = fmaf(d6, f6.y, accy);
        accx = fmaf(d7, f7.x, accx); accy = fmaf(d7, f7.y, accy);
    }
    for (; k < end; k++) {
        int s = g_eidx[k];
        float ds = g_dinv[s];
        unsigned u = xwl[(unsigned)s << 5];
        float2 f = __half22float2(*(__half2*)&u);
        accx = fmaf(ds, f.x, accx);
        accy = fmaf(ds, f.y, accy);
    }

    float sc = g_dinv[w];
    unsigned su = xwl[(unsigned)w << 5];
    float2 sf = __half22float2(*(__half2*)&su);
    accx = fmaf(sc, sf.x, accx);
    accy = fmaf(sc, sf.y, accy);

    float bx = b1[2 * lane], by = b1[2 * lane + 1];
    float2 r;
    r.x = fmaxf(fmaf(accx, sc, bx), 0.0f);
    r.y = fmaxf(fmaf(accy, sc, by), 0.0f);
    ((float2*)g_h)[(unsigned)w * 32 + lane] = r;
}

// ---------------- GEMM2: hws = (h @ W2) * dinv[row], fp16 out ---------------
__global__ void k_gemm2(const float* __restrict__ W, int n) {
    __shared__ float ws[F1 * F2];  // 10.24 KB
    int tid = threadIdx.x;
    for (int i = tid; i < F1 * F2; i += 320) ws[i] = W[i];
    __syncthreads();

    int sub = tid / 5;
    int cg  = (tid % 5) * 8;
    int r0 = blockIdx.x * 128 + sub;
    int r1 = r0 + 64;
    if (r0 >= n) return;
    bool v1 = (r1 < n);

    float a00 = 0.f, a01 = 0.f, a02 = 0.f, a03 = 0.f;
    float a04 = 0.f, a05 = 0.f, a06 = 0.f, a07 = 0.f;
    float a10 = 0.f, a11 = 0.f, a12 = 0.f, a13 = 0.f;
    float a14 = 0.f, a15 = 0.f, a16 = 0.f, a17 = 0.f;

    const float4* hr0 = (const float4*)((const float*)g_h + (size_t)r0 * F1);
    const float4* hr1 = (const float4*)((const float*)g_h + (size_t)(v1 ? r1 : r0) * F1);
#pragma unroll 4
    for (int k4 = 0; k4 < F1 / 4; k4++) {
        float4 ha = hr0[k4];
        float4 hb = hr1[k4];
        float h0[4] = {ha.x, ha.y, ha.z, ha.w};
        float h1[4] = {hb.x, hb.y, hb.z, hb.w};
#pragma unroll
        for (int kk = 0; kk < 4; kk++) {
            const float4* wr = (const float4*)(ws + (k4 * 4 + kk) * F2 + cg);
            float4 wa = wr[0];
            float4 wb = wr[1];
            float p0 = h0[kk], p1 = h1[kk];
            a00 = fmaf(p0, wa.x, a00); a10 = fmaf(p1, wa.x, a10);
            a01 = fmaf(p0, wa.y, a01); a11 = fmaf(p1, wa.y, a11);
            a02 = fmaf(p0, wa.z, a02); a12 = fmaf(p1, wa.z, a12);
            a03 = fmaf(p0, wa.w, a03); a13 = fmaf(p1, wa.w, a13);
            a04 = fmaf(p0, wb.x, a04); a14 = fmaf(p1, wb.x, a14);
            a05 = fmaf(p0, wb.y, a05); a15 = fmaf(p1, wb.y, a15);
            a06 = fmaf(p0, wb.z, a06); a16 = fmaf(p1, wb.z, a16);
            a07 = fmaf(p0, wb.w, a07); a17 = fmaf(p1, wb.w, a17);
        }
    }

    float s0 = g_dinv[r0];
    {
        __half2 h0 = __float22half2_rn(make_float2(a00 * s0, a01 * s0));
        __half2 h1 = __float22half2_rn(make_float2(a02 * s0, a03 * s0));
        __half2 h2 = __float22half2_rn(make_float2(a04 * s0, a05 * s0));
        __half2 h3 = __float22half2_rn(make_float2(a06 * s0, a07 * s0));
        uint4 pk;
        pk.x = *(unsigned*)&h0; pk.y = *(unsigned*)&h1;
        pk.z = *(unsigned*)&h2; pk.w = *(unsigned*)&h3;
        ((uint4*)g_hwsh)[(size_t)r0 * 5 + (cg >> 3)] = pk;
    }
    if (v1) {
        float s1 = g_dinv[r1];
        __half2 h0 = __float22half2_rn(make_float2(a10 * s1, a11 * s1));
        __half2 h1 = __float22half2_rn(make_float2(a12 * s1, a13 * s1));
        __half2 h2 = __float22half2_rn(make_float2(a14 * s1, a15 * s1));
        __half2 h3 = __float22half2_rn(make_float2(a16 * s1, a17 * s1));
        uint4 pk;
        pk.x = *(unsigned*)&h0; pk.y = *(unsigned*)&h1;
        pk.z = *(unsigned*)&h2; pk.w = *(unsigned*)&h3;
        ((uint4*)g_hwsh)[(size_t)r1 * 5 + (cg >> 3)] = pk;
    }
}

// ---------------- aggregation layer2 + log_softmax (32-bit addressing) ------
__global__ void k_agg2(const float* __restrict__ b2, float* __restrict__ out, int n) {
    int lane = threadIdx.x & 31;
    int w = blockIdx.x * 8 + (threadIdx.x >> 5);
    if (w >= n) return;

    bool act = (lane < F2 / 2);
    int li = act ? lane : 0;
    const unsigned* hwl = ((const unsigned*)g_hwsh) + li;   // lane base
    int beg = g_off[w], end = g_off[w + 1];

    float accx = 0.f, accy = 0.f;
    int k = beg;
    for (; k + 7 < end; k += 8) {
        unsigned o0 = (unsigned)g_eidx[k]     * 20u;
        unsigned o1 = (unsigned)g_eidx[k + 1] * 20u;
        unsigned o2 = (unsigned)g_eidx[k + 2] * 20u;
        unsigned o3 = (unsigned)g_eidx[k + 3] * 20u;
        unsigned o4 = (unsigned)g_eidx[k + 4] * 20u;
        unsigned o5 = (unsigned)g_eidx[k + 5] * 20u;
        unsigned o6 = (unsigned)g_eidx[k + 6] * 20u;
        unsigned o7 = (unsigned)g_eidx[k + 7] * 20u;
        unsigned u0 = hwl[o0];
        unsigned u1 = hwl[o1];
        unsigned u2 = hwl[o2];
        unsigned u3 = hwl[o3];
        unsigned u4 = hwl[o4];
        unsigned u5 = hwl[o5];
        unsigned u6 = hwl[o6];
        unsigned u7 = hwl[o7];
        float2 f0 = __half22float2(*(__half2*)&u0);
        float2 f1 = __half22float2(*(__half2*)&u1);
        float2 f2 = __half22float2(*(__half2*)&u2);
        float2 f3 = __half22float2(*(__half2*)&u3);
        float2 f4 = __half22float2(*(__half2*)&u4);
        float2 f5 = __half22float2(*(__half2*)&u5);
        float2 f6 = __half22float2(*(__half2*)&u6);
        float2 f7 = __half22float2(*(__half2*)&u7);
        accx += ((f0.x + f1.x) + (f2.x + f3.x)) + ((f4.x + f5.x) + (f6.x + f7.x));
        accy += ((f0.y + f1.y) + (f2.y + f3.y)) + ((f4.y + f5.y) + (f6.y + f7.y));
    }
    for (; k < end; k++) {
        unsigned u = hwl[(unsigned)g_eidx[k] * 20u];
        float2 f = __half22float2(*(__half2*)&u);
        accx += f.x;
        accy += f.y;
    }

    {
        unsigned su = hwl[(unsigned)w * 20u];
        float2 sf = __half22float2(*(__half2*)&su);
        accx += sf.x;
        accy += sf.y;
    }

    float sc = g_dinv[w];
    float zx = fmaf(accx, sc, b2[2 * li]);
    float zy = fmaf(accy, sc, b2[2 * li + 1]);

    float m = act ? fmaxf(zx, zy) : -1e30f;
#pragma unroll
    for (int o = 16; o > 0; o >>= 1)
        m = fmaxf(m, __shfl_xor_sync(0xFFFFFFFFu, m, o));

    float sum = act ? (expf(zx - m) + expf(zy - m)) : 0.0f;
#pragma unroll
    for (int o = 16; o > 0; o >>= 1)
        sum += __shfl_xor_sync(0xFFFFFFFFu, sum, o);

    float lse = m + logf(sum);
    if (act) {
        float2* o2 = (float2*)(out + (unsigned)w * F2 + 2 * li);
        *o2 = make_float2(zx - lse, zy - lse);
    }
}

// ---------------- launcher --------------------------------------------------
extern "C" void kernel_launch(void* const* d_in, const int* in_sizes, int n_in,
                              void* d_out, int out_size) {
    const float* x    = (const float*)d_in[0];
    const int*   ei32 = (const int*)d_in[1];
    const float* W1   = (const float*)d_in[2];
    const float* b1   = (const float*)d_in[3];
    const float* W2   = (const float*)d_in[4];
    const float* b2   = (const float*)d_in[5];
    float*       out  = (float*)d_out;

    int n = in_sizes[0] / FIN;       // 100000
    int E = in_sizes[1] / 2;         // 1600000

    const int B = 256;
    int gn = (n + B - 1) / B;
    int ge = (E + B - 1) / B;
    int nb = (n + 1023) / 1024;      // 98
    int ga = (n + 7) / 8;
    int gemmBlocks = (n + 127) / 128;

    k_zero_probe <<<gn + 1, B>>>(ei32, E, n);
    k_gemm1_hist <<<gemmBlocks + ge, B>>>(x, W1, ei32, E, n, gemmBlocks);
    k_scan       <<<nb, 1024>>>(n, nb);
    k_place      <<<ge, B>>>(ei32, E, n);      // 4th launch -> ncu captures
    k_agg1       <<<ga, B>>>(b1, n);
    k_gemm2      <<<(n + 127) / 128, 320>>>(W2, n);
    k_agg2       <<<ga, B>>>(b2, out, n);
}